// round 1
// baseline (speedup 1.0000x reference)
#include <cuda_runtime.h>
#include <math.h>

#define PS 32
#define NB 36
#define WPB 8                 // warps (patches) per block
#define THREADS (WPB * 32)
#define HSTRIDE 37            // 37 = 5 mod 32, invertible -> conflict-free per-lane hist

__global__ __launch_bounds__(THREADS)
void orient_kernel(const float* __restrict__ x,
                   const float* __restrict__ gk,
                   float* __restrict__ out,
                   int B)
{
    __shared__ float s_gk[PS * PS];
    __shared__ float s_priv[WPB][32 * HSTRIDE];
    __shared__ float s_hist[WPB][40];
    __shared__ float s_sm[WPB][40];

    const int tid  = threadIdx.x;
    const int w    = tid >> 5;
    const int lane = tid & 31;
    const int patch = blockIdx.x * WPB + w;
    const bool valid = (patch < B);

    // stage gk (shared by all patches)
    for (int i = tid; i < PS * PS; i += THREADS) s_gk[i] = gk[i];

    float* priv = s_priv[w];
    #pragma unroll
    for (int b = 0; b < HSTRIDE; b++) priv[lane * HSTRIDE + b] = 0.0f;
    __syncthreads();

    const float PI_F  = 3.14159265358979323846f;   // rounds to fp32 pi
    const float TPI_F = 6.28318530717958647692f;   // fp32 2*pi

    const unsigned FULL = 0xffffffffu;
    const int srcL = (lane > 0)  ? lane - 1 : 0;   // replicate-pad left
    const int srcR = (lane < 31) ? lane + 1 : 31;  // replicate-pad right

    const float* xp = x + (size_t)(valid ? patch : 0) * (PS * PS);

    // rolling 3-row window, lane = column
    float cur = xp[lane];            // row 0
    float prv = cur;                 // clamped row -1
    float nxt = xp[PS + lane];       // row 1

    #pragma unroll
    for (int r = 0; r < PS; r++) {
        float xl = __shfl_sync(FULL, cur, srcL);
        float xr = __shfl_sync(FULL, cur, srcR);
        // gx = 0.5*(left - right), gy = 0.5*(up - down)  (exact fp32, no fusion)
        float gxv = __fmul_rn(0.5f, __fsub_rn(xl, xr));
        float gyv = __fmul_rn(0.5f, __fsub_rn(prv, nxt));
        float m2  = __fadd_rn(__fadd_rn(__fmul_rn(gxv, gxv),
                                        __fmul_rn(gyv, gyv)), 1e-10f);
        float mag = __fmul_rn(sqrtf(m2), s_gk[r * PS + lane]); // IEEE sqrt
        float ori = atan2f(gyv, gxv);
        float obig = __fdiv_rn(__fmul_rn((float)NB, __fadd_rn(ori, PI_F)), TPI_F);
        float bo0  = floorf(obig);
        float wo1  = __fsub_rn(obig, bo0);
        int   b    = (int)bo0;
        if (b >= NB) b -= NB;       // obig can hit exactly 36.0 at ori = +pi
        if (b < 0)   b = 0;         // defensive (shouldn't occur)
        float wv   = __fmul_rn(__fsub_rn(1.0f, wo1), mag);

        int hidx = lane * HSTRIDE + b;            // bank-conflict-free per lane
        priv[hidx] = __fadd_rn(priv[hidx], wv);

        prv = cur;
        cur = nxt;
        nxt = (r + 2 < PS) ? xp[(r + 2) * PS + lane] : cur;
    }
    __syncwarp();

    // reduce 32 private hists -> 36 bins (pass 1: bins 0..31, pass 2: bins 32..35)
    float s = 0.0f;
    #pragma unroll
    for (int t = 0; t < 32; t++) s = __fadd_rn(s, priv[t * HSTRIDE + lane]);
    const int l2 = 32 + (lane & 3);               // broadcast-friendly
    float s2 = 0.0f;
    #pragma unroll
    for (int t = 0; t < 32; t++) s2 = __fadd_rn(s2, priv[t * HSTRIDE + l2]);

    s_hist[w][lane] = s;
    if (lane < 4) s_hist[w][32 + lane] = s2;
    __syncwarp();

    // smoothing: zero-padded conv [0.33, 0.34, 0.33] (left-assoc adds like ref)
    {
        float h0 = s_hist[w][lane];
        float hm = (lane > 0) ? s_hist[w][lane - 1] : 0.0f;
        float hp = s_hist[w][lane + 1];           // lane 31 -> bin 32, valid
        float a  = __fmul_rn(0.33f, hm);
        float bb = __fmul_rn(0.34f, h0);
        float c  = __fmul_rn(0.33f, hp);
        s_sm[w][lane] = __fadd_rn(__fadd_rn(a, bb), c);
    }
    if (lane < 4) {
        int i = 32 + lane;
        float h0 = s_hist[w][i];
        float hm = s_hist[w][i - 1];
        float hp = (i < NB - 1) ? s_hist[w][i + 1] : 0.0f;
        float a  = __fmul_rn(0.33f, hm);
        float bb = __fmul_rn(0.34f, h0);
        float c  = __fmul_rn(0.33f, hp);
        s_sm[w][i] = __fadd_rn(__fadd_rn(a, bb), c);
    }
    __syncwarp();

    if (lane == 0 && valid) {
        // first-occurrence argmax (strict > like jnp.argmax)
        float best = s_sm[w][0];
        int   bi   = 0;
        #pragma unroll
        for (int i = 1; i < NB; i++) {
            float v = s_sm[w][i];
            if (v > best) { best = v; bi = i; }
        }
        float ang = __fsub_rn(__fdiv_rn(__fmul_rn(TPI_F, (float)bi), (float)NB), PI_F);
        out[patch] = -ang;
    }
}

extern "C" void kernel_launch(void* const* d_in, const int* in_sizes, int n_in,
                              void* d_out, int out_size)
{
    const float* x  = (const float*)d_in[0];
    const float* gk = (const float*)d_in[1];
    float* out = (float*)d_out;
    int B = in_sizes[0] / (PS * PS);
    int nblocks = (B + WPB - 1) / WPB;
    orient_kernel<<<nblocks, THREADS>>>(x, gk, out, B);
}

// round 4
// speedup vs baseline: 1.1184x; 1.1184x over previous
#include <cuda_runtime.h>
#include <math.h>

#define PS 32
#define NB 36
#define WPB 8
#define THREADS (WPB * 32)
#define NCOPY 16                // private-hist copies per warp (2 lanes share one)

__global__ __launch_bounds__(THREADS, 8)
void orient_kernel(const float* __restrict__ x,
                   const float* __restrict__ gk,
                   float* __restrict__ out,
                   int B)
{
    __shared__ float s_gk[PS * PS];
    __shared__ float s_priv[WPB][NB * NCOPY];   // [b*16 + copy]
    __shared__ float s_hist[WPB][40];
    __shared__ float s_sm[WPB][40];

    const int tid   = threadIdx.x;
    const int w     = tid >> 5;
    const int lane  = tid & 31;
    const int patch = blockIdx.x * WPB + w;
    const bool valid = (patch < B);

    for (int i = tid; i < PS * PS; i += THREADS) s_gk[i] = gk[i];

    float* priv = s_priv[w];
    #pragma unroll
    for (int i = lane; i < NB * NCOPY; i += 32) priv[i] = 0.0f;
    __syncthreads();

    const float PI_F  = 3.14159265358979323846f;   // fp32 pi
    const float TPI_F = 6.28318530717958647692f;   // fp32 2*pi

    const unsigned FULL = 0xffffffffu;
    const int srcL = (lane > 0)  ? lane - 1 : 0;   // replicate-pad left
    const int srcR = (lane < 31) ? lane + 1 : 31;  // replicate-pad right
    const int copy = lane;                          // only lanes 0..15 use it

    const float* xp = x + (size_t)(valid ? patch : 0) * (PS * PS);

    // rolling 3-row window, lane = column
    float cur = xp[lane];
    float prv = cur;
    float nxt = xp[PS + lane];

    #pragma unroll
    for (int r = 0; r < PS; r++) {
        float xl = __shfl_sync(FULL, cur, srcL);
        float xr = __shfl_sync(FULL, cur, srcR);
        // EXACT reference math (bit-matched chain; do not approximate)
        float gxv = __fmul_rn(0.5f, __fsub_rn(xl, xr));
        float gyv = __fmul_rn(0.5f, __fsub_rn(prv, nxt));
        float m2  = __fadd_rn(__fadd_rn(__fmul_rn(gxv, gxv),
                                        __fmul_rn(gyv, gyv)), 1e-10f);
        float mag = __fmul_rn(sqrtf(m2), s_gk[r * PS + lane]);
        float ori = atan2f(gyv, gxv);
        float obig = __fdiv_rn(__fmul_rn((float)NB, __fadd_rn(ori, PI_F)), TPI_F);
        float bo0  = floorf(obig);
        float wo1  = __fsub_rn(obig, bo0);
        int   b    = (int)bo0;
        if (b >= NB) b -= NB;                         // ori == +pi edge
        float wv   = __fmul_rn(__fsub_rn(1.0f, wo1), mag);

        // lane i<16 performs its own update AND partner (i+16)'s update,
        // sequentially in one thread -> race-free by construction.
        int   b2  = __shfl_down_sync(FULL, b, 16);
        float wv2 = __shfl_down_sync(FULL, wv, 16);
        if (lane < 16) {
            int h1 = b  * NCOPY + copy;               // bank = copy + 16*(b&1)
            priv[h1] += wv;
            int h2 = b2 * NCOPY + copy;
            priv[h2] += wv2;
        }

        prv = cur;
        cur = nxt;
        nxt = (r + 2 < PS) ? xp[(r + 2) * PS + lane] : cur;
    }
    __syncwarp();

    // reduce 16 copies -> 36 bins.
    // bank of priv[bin*16 + cc] = 16*(bin&1) + cc ; cc = (c + lane>>1)&15 is
    // distinct across the 16 lane-pairs, parities split the halves -> conflict-free.
    const int rot = lane >> 1;
    float s1 = 0.0f;
    #pragma unroll
    for (int c = 0; c < NCOPY; c++) {
        int cc = (c + rot) & 15;
        s1 += priv[lane * NCOPY + cc];
    }
    const int l2 = 32 + (lane & 3);
    float s2 = 0.0f;
    #pragma unroll
    for (int c = 0; c < NCOPY; c++) {
        int cc = (c + rot) & 15;
        s2 += priv[l2 * NCOPY + cc];
    }
    s_hist[w][lane] = s1;
    if (lane < 4) s_hist[w][32 + lane] = s2;
    __syncwarp();

    // zero-padded smoothing [0.33, 0.34, 0.33] (left-assoc like R1)
    {
        float h0 = s_hist[w][lane];
        float hm = (lane > 0) ? s_hist[w][lane - 1] : 0.0f;
        float hp = s_hist[w][lane + 1];
        float a  = __fmul_rn(0.33f, hm);
        float bb = __fmul_rn(0.34f, h0);
        float c  = __fmul_rn(0.33f, hp);
        s_sm[w][lane] = __fadd_rn(__fadd_rn(a, bb), c);
    }
    if (lane < 4) {
        int i = 32 + lane;
        float h0 = s_hist[w][i];
        float hm = s_hist[w][i - 1];
        float hp = (i < NB - 1) ? s_hist[w][i + 1] : 0.0f;
        float a  = __fmul_rn(0.33f, hm);
        float bb = __fmul_rn(0.34f, h0);
        float c  = __fmul_rn(0.33f, hp);
        s_sm[w][i] = __fadd_rn(__fadd_rn(a, bb), c);
    }
    __syncwarp();

    if (lane == 0 && valid) {
        float best = s_sm[w][0];
        int   bi   = 0;
        #pragma unroll
        for (int i = 1; i < NB; i++) {
            float v = s_sm[w][i];
            if (v > best) { best = v; bi = i; }
        }
        float ang = __fsub_rn(__fdiv_rn(__fmul_rn(TPI_F, (float)bi), (float)NB), PI_F);
        out[patch] = -ang;
    }
}

extern "C" void kernel_launch(void* const* d_in, const int* in_sizes, int n_in,
                              void* d_out, int out_size)
{
    const float* x  = (const float*)d_in[0];
    const float* gk = (const float*)d_in[1];
    float* out = (float*)d_out;
    int B = in_sizes[0] / (PS * PS);
    int nblocks = (B + WPB - 1) / WPB;
    orient_kernel<<<nblocks, THREADS>>>(x, gk, out, B);
}

// round 5
// speedup vs baseline: 1.1923x; 1.0661x over previous
#include <cuda_runtime.h>
#include <math.h>

#define PS 32
#define NB 36
#define WPB 8                  // warps (patches) per block
#define THREADS (WPB * 32)
#define NCOPY 16               // private-hist copies per warp

__global__ __launch_bounds__(THREADS, 7)
void orient_kernel(const float* __restrict__ x,
                   const float* __restrict__ gk,
                   float* __restrict__ out,
                   int B)
{
    __shared__ float s_gk[PS * PS];
    __shared__ float s_priv[WPB][NB * NCOPY];   // [b*16 + copy]
    __shared__ float s_hist[WPB][40];
    __shared__ float s_sm[WPB][40];

    const int tid   = threadIdx.x;
    const int w     = tid >> 5;
    const int lane  = tid & 31;
    const int patch = blockIdx.x * WPB + w;
    const bool valid = (patch < B);

    for (int i = tid; i < PS * PS; i += THREADS) s_gk[i] = gk[i];

    float* priv = s_priv[w];
    #pragma unroll
    for (int i = lane; i < NB * NCOPY; i += 32) priv[i] = 0.0f;
    __syncthreads();

    const float PI_F  = 3.14159265358979323846f;   // fp32 pi
    const float TPI_F = 6.28318530717958647692f;   // fp32 2*pi
    const unsigned FULL = 0xffffffffu;

    const int h    = lane >> 4;        // row-half: 0 -> rows 0..15, 1 -> rows 16..31
    const int hl   = lane & 15;        // column-pair index: owns cols 2hl, 2hl+1
    const int col0 = 2 * hl;

    const float* xp = x + (size_t)(valid ? patch : 0) * (PS * PS);
    const float* xh = xp + h * 16 * PS;           // base row of this half
    const int gkb   = h * 16 * PS + col0;         // gk base index for this half

    // rolling 3-row float2 window (per half)
    float2 cur = *(const float2*)(xh + col0);                 // row h*16
    float2 prv;
    if (h == 0) prv = cur;                                     // replicate row -1
    else        prv = *(const float2*)(xh - PS + col0);        // row 15
    float2 nxt = *(const float2*)(xh + PS + col0);             // row h*16+1

    #pragma unroll
    for (int r = 0; r < 16; r++) {
        // gx neighbor exchange within each 16-lane half (same patch, different rows)
        float Lup = __shfl_up_sync(FULL, cur.y, 1, 16);   // prev lane's col 2hl-1
        float Rdn = __shfl_down_sync(FULL, cur.x, 1, 16); // next lane's col 2hl+2
        float left0  = (hl == 0)  ? cur.x : Lup;          // replicate col -1 -> col 0
        float right1 = (hl == 15) ? cur.y : Rdn;          // replicate col 32 -> col 31

        float2 g2 = *(const float2*)(s_gk + gkb + r * PS);

        // ---- pixel 0 (col 2hl) ----  FROZEN bin chain (bit-exact vs XLA)
        float gx0 = __fmul_rn(0.5f, __fsub_rn(left0, cur.y));
        float gy0 = __fmul_rn(0.5f, __fsub_rn(prv.x, nxt.x));
        float ori0  = atan2f(gy0, gx0);
        float obig0 = __fdiv_rn(__fmul_rn((float)NB, __fadd_rn(ori0, PI_F)), TPI_F);
        float bo00  = floorf(obig0);
        float wo10  = __fsub_rn(obig0, bo00);
        int   bx    = (int)bo00;
        if (bx >= NB) bx -= NB;
        // continuous magnitude path (trimmed)
        float m20  = fmaf(gx0, gx0, fmaf(gy0, gy0, 1e-10f));
        float mag0 = m20 * rsqrtf(m20) * g2.x;
        float wx   = fmaf(-wo10, mag0, mag0);             // (1 - wo1) * mag

        // ---- pixel 1 (col 2hl+1) ----
        float gx1 = __fmul_rn(0.5f, __fsub_rn(cur.x, right1));
        float gy1 = __fmul_rn(0.5f, __fsub_rn(prv.y, nxt.y));
        float ori1  = atan2f(gy1, gx1);
        float obig1 = __fdiv_rn(__fmul_rn((float)NB, __fadd_rn(ori1, PI_F)), TPI_F);
        float bo01  = floorf(obig1);
        float wo11  = __fsub_rn(obig1, bo01);
        int   by    = (int)bo01;
        if (by >= NB) by -= NB;
        float m21  = fmaf(gx1, gx1, fmaf(gy1, gy1, 1e-10f));
        float mag1 = m21 * rsqrtf(m21) * g2.y;
        float wy   = fmaf(-wo11, mag1, mag1);

        // hist: lane i<16 also applies partner (i+16)'s updates, sequentially
        int   bx2 = __shfl_down_sync(FULL, bx, 16);
        int   by2 = __shfl_down_sync(FULL, by, 16);
        float wx2 = __shfl_down_sync(FULL, wx, 16);
        float wy2 = __shfl_down_sync(FULL, wy, 16);
        if (lane < 16) {                                  // copy = hl, bank = hl+16*(b&1)
            priv[bx  * NCOPY + hl] += wx;
            priv[by  * NCOPY + hl] += wy;
            priv[bx2 * NCOPY + hl] += wx2;
            priv[by2 * NCOPY + hl] += wy2;
        }

        prv = cur;
        cur = nxt;
        if (r < 15) {
            // next iteration's row+1: global row g+2 = h*16 + r + 2
            if (r < 14 || h == 0) {
                nxt = *(const float2*)(xh + (r + 2) * PS + col0);
            } else {
                nxt = cur;                                // replicate row 32 -> row 31
            }
        }
    }
    __syncwarp();

    // reduce 16 copies -> 36 bins (same conflict-free rotation as R4)
    const int rot = lane >> 1;
    float s1 = 0.0f;
    #pragma unroll
    for (int c = 0; c < NCOPY; c++) {
        int cc = (c + rot) & 15;
        s1 += priv[lane * NCOPY + cc];
    }
    const int l2 = 32 + (lane & 3);
    float s2 = 0.0f;
    #pragma unroll
    for (int c = 0; c < NCOPY; c++) {
        int cc = (c + rot) & 15;
        s2 += priv[l2 * NCOPY + cc];
    }
    s_hist[w][lane] = s1;
    if (lane < 4) s_hist[w][32 + lane] = s2;
    __syncwarp();

    // zero-padded smoothing [0.33, 0.34, 0.33]
    {
        float h0 = s_hist[w][lane];
        float hm = (lane > 0) ? s_hist[w][lane - 1] : 0.0f;
        float hp = s_hist[w][lane + 1];
        float a  = __fmul_rn(0.33f, hm);
        float bb = __fmul_rn(0.34f, h0);
        float c  = __fmul_rn(0.33f, hp);
        s_sm[w][lane] = __fadd_rn(__fadd_rn(a, bb), c);
    }
    if (lane < 4) {
        int i = 32 + lane;
        float h0 = s_hist[w][i];
        float hm = s_hist[w][i - 1];
        float hp = (i < NB - 1) ? s_hist[w][i + 1] : 0.0f;
        float a  = __fmul_rn(0.33f, hm);
        float bb = __fmul_rn(0.34f, h0);
        float c  = __fmul_rn(0.33f, hp);
        s_sm[w][i] = __fadd_rn(__fadd_rn(a, bb), c);
    }
    __syncwarp();

    if (lane == 0 && valid) {
        float best = s_sm[w][0];
        int   bi   = 0;
        #pragma unroll
        for (int i = 1; i < NB; i++) {
            float v = s_sm[w][i];
            if (v > best) { best = v; bi = i; }
        }
        float ang = __fsub_rn(__fdiv_rn(__fmul_rn(TPI_F, (float)bi), (float)NB), PI_F);
        out[patch] = -ang;
    }
}

extern "C" void kernel_launch(void* const* d_in, const int* in_sizes, int n_in,
                              void* d_out, int out_size)
{
    const float* x  = (const float*)d_in[0];
    const float* gk = (const float*)d_in[1];
    float* out = (float*)d_out;
    int B = in_sizes[0] / (PS * PS);
    int nblocks = (B + WPB - 1) / WPB;
    orient_kernel<<<nblocks, THREADS>>>(x, gk, out, B);
}

// round 6
// speedup vs baseline: 1.2378x; 1.0382x over previous
#include <cuda_runtime.h>
#include <math.h>

#define PS 32
#define NB 36
#define WPB 8
#define THREADS (WPB * 32)
#define NCOPY 16

typedef unsigned long long u64p;

__device__ __forceinline__ u64p pk(float lo, float hi) {
    u64p r; asm("mov.b64 %0, {%1, %2};" : "=l"(r) : "f"(lo), "f"(hi)); return r;
}
__device__ __forceinline__ void upk(u64p v, float& lo, float& hi) {
    asm("mov.b64 {%0, %1}, %2;" : "=f"(lo), "=f"(hi) : "l"(v));
}
__device__ __forceinline__ u64p add2(u64p a, u64p b) {
    u64p r; asm("add.rn.f32x2 %0, %1, %2;" : "=l"(r) : "l"(a), "l"(b)); return r;
}
__device__ __forceinline__ u64p mul2(u64p a, u64p b) {
    u64p r; asm("mul.rn.f32x2 %0, %1, %2;" : "=l"(r) : "l"(a), "l"(b)); return r;
}
__device__ __forceinline__ u64p fma2(u64p a, u64p b, u64p c) {
    u64p r; asm("fma.rn.f32x2 %0, %1, %2, %3;" : "=l"(r) : "l"(a), "l"(b), "l"(c)); return r;
}

#define PKC(v) ((((u64p)__float_as_uint(v)) << 32) | (u64p)__float_as_uint(v))

__global__ __launch_bounds__(THREADS, 7)
void orient_kernel(const float* __restrict__ x,
                   const float* __restrict__ gk,
                   float* __restrict__ out,
                   int B)
{
    __shared__ float s_gk[PS * PS];
    __shared__ float s_priv[WPB][NB * NCOPY];
    __shared__ float s_hist[WPB][40];
    __shared__ float s_sm[WPB][40];

    const int tid   = threadIdx.x;
    const int w     = tid >> 5;
    const int lane  = tid & 31;
    const int patch = blockIdx.x * WPB + w;
    const bool valid = (patch < B);

    for (int i = tid; i < PS * PS; i += THREADS) s_gk[i] = gk[i];

    float* priv = s_priv[w];
    #pragma unroll
    for (int i = lane; i < NB * NCOPY; i += 32) priv[i] = 0.0f;
    __syncthreads();

    const float PI_F  = 3.14159265358979323846f;
    const float TPI_F = 6.28318530717958647692f;
    const unsigned FULL = 0xffffffffu;

    const u64p HALF2 = PKC(0.5f);
    const u64p NEG12 = PKC(-1.0f);
    const u64p PI2   = PKC(PI_F);
    const u64p C362  = PKC(36.0f);
    const u64p EPS2  = PKC(1e-10f);
    const u64p ONE2  = PKC(1.0f);

    const int h    = lane >> 4;        // row-half
    const int hl   = lane & 15;        // column-pair index
    const int col0 = 2 * hl;

    const float* xp = x + (size_t)(valid ? patch : 0) * (PS * PS);
    const float* xh = xp + h * 16 * PS;
    const int gkb   = h * 16 * PS + col0;

    float2 cur = *(const float2*)(xh + col0);
    float2 prv = (h == 0) ? cur : *(const float2*)(xh - PS + col0);
    float2 nxt = *(const float2*)(xh + PS + col0);

    #pragma unroll
    for (int r = 0; r < 16; r++) {
        float Lup = __shfl_up_sync(FULL, cur.y, 1, 16);
        float Rdn = __shfl_down_sync(FULL, cur.x, 1, 16);
        float left0  = (hl == 0)  ? cur.x : Lup;
        float right1 = (hl == 15) ? cur.y : Rdn;

        // FROZEN gradients, packed: fma(-1,b,a) == __fsub_rn(a,b) bitwise,
        // mul2(.,0.5) == __fmul_rn(0.5,.) bitwise per element.
        u64p prv2 = pk(prv.x, prv.y);
        u64p nxt2 = pk(nxt.x, nxt.y);
        u64p gy2  = mul2(fma2(nxt2, NEG12, prv2), HALF2);   // 0.5*(prv-nxt)
        u64p ga   = pk(left0, cur.x);
        u64p gb   = pk(cur.y, right1);
        u64p gx2  = mul2(fma2(gb, NEG12, ga), HALF2);       // 0.5*(left-right)

        float gx0, gx1, gy0, gy1;
        upk(gx2, gx0, gx1);
        upk(gy2, gy0, gy1);

        // FROZEN: libdevice atan2f (bit-exact vs XLA)
        float ori0 = atan2f(gy0, gx0);
        float ori1 = atan2f(gy1, gx1);

        // FROZEN chain: rn(36 * rn(ori+pi)) packed, then scalar IEEE div
        u64p t36 = mul2(add2(pk(ori0, ori1), PI2), C362);
        float ta, tb; upk(t36, ta, tb);
        float obig0 = __fdiv_rn(ta, TPI_F);
        float obig1 = __fdiv_rn(tb, TPI_F);
        float bo00 = floorf(obig0);
        float bo01 = floorf(obig1);
        int bx = (int)bo00; if (bx >= NB) bx -= NB;
        int by = (int)bo01; if (by >= NB) by -= NB;

        // continuous path (re-roundable): wo1, mag, wv
        u64p wo2  = fma2(pk(bo00, bo01), NEG12, pk(obig0, obig1)); // obig-bo0
        u64p m2v  = fma2(gx2, gx2, fma2(gy2, gy2, EPS2));
        float m20, m21; upk(m2v, m20, m21);
        u64p rs2  = pk(rsqrtf(m20), rsqrtf(m21));
        u64p gk2  = *(const u64p*)(s_gk + gkb + r * PS);           // LDS.64
        u64p mag2 = mul2(mul2(m2v, rs2), gk2);
        u64p wv2  = mul2(fma2(wo2, NEG12, ONE2), mag2);            // (1-wo1)*mag
        float wx, wy; upk(wv2, wx, wy);

        // proven hist: lanes<16 apply own + partner updates sequentially
        int   bx2 = __shfl_down_sync(FULL, bx, 16);
        int   by2 = __shfl_down_sync(FULL, by, 16);
        float wx2 = __shfl_down_sync(FULL, wx, 16);
        float wy2 = __shfl_down_sync(FULL, wy, 16);
        if (lane < 16) {
            priv[bx  * NCOPY + hl] += wx;
            priv[by  * NCOPY + hl] += wy;
            priv[bx2 * NCOPY + hl] += wx2;
            priv[by2 * NCOPY + hl] += wy2;
        }

        prv = cur;
        cur = nxt;
        if (r < 15) {
            if (r < 14 || h == 0) nxt = *(const float2*)(xh + (r + 2) * PS + col0);
            else                  nxt = cur;     // replicate last row
        }
    }
    __syncwarp();

    // reduce 16 copies -> 36 bins (conflict-free rotation)
    const int rot = lane >> 1;
    float s1 = 0.0f;
    #pragma unroll
    for (int c = 0; c < NCOPY; c++) {
        int cc = (c + rot) & 15;
        s1 += priv[lane * NCOPY + cc];
    }
    const int l2 = 32 + (lane & 3);
    float s2 = 0.0f;
    #pragma unroll
    for (int c = 0; c < NCOPY; c++) {
        int cc = (c + rot) & 15;
        s2 += priv[l2 * NCOPY + cc];
    }
    s_hist[w][lane] = s1;
    if (lane < 4) s_hist[w][32 + lane] = s2;
    __syncwarp();

    // zero-padded smoothing [0.33, 0.34, 0.33]
    {
        float h0 = s_hist[w][lane];
        float hm = (lane > 0) ? s_hist[w][lane - 1] : 0.0f;
        float hp = s_hist[w][lane + 1];
        float a  = __fmul_rn(0.33f, hm);
        float bb = __fmul_rn(0.34f, h0);
        float c  = __fmul_rn(0.33f, hp);
        s_sm[w][lane] = __fadd_rn(__fadd_rn(a, bb), c);
    }
    if (lane < 4) {
        int i = 32 + lane;
        float h0 = s_hist[w][i];
        float hm = s_hist[w][i - 1];
        float hp = (i < NB - 1) ? s_hist[w][i + 1] : 0.0f;
        float a  = __fmul_rn(0.33f, hm);
        float bb = __fmul_rn(0.34f, h0);
        float c  = __fmul_rn(0.33f, hp);
        s_sm[w][i] = __fadd_rn(__fadd_rn(a, bb), c);
    }
    __syncwarp();

    if (lane == 0 && valid) {
        float best = s_sm[w][0];
        int   bi   = 0;
        #pragma unroll
        for (int i = 1; i < NB; i++) {
            float v = s_sm[w][i];
            if (v > best) { best = v; bi = i; }
        }
        float ang = __fsub_rn(__fdiv_rn(__fmul_rn(TPI_F, (float)bi), (float)NB), PI_F);
        out[patch] = -ang;
    }
}

extern "C" void kernel_launch(void* const* d_in, const int* in_sizes, int n_in,
                              void* d_out, int out_size)
{
    const float* x  = (const float*)d_in[0];
    const float* gk = (const float*)d_in[1];
    float* out = (float*)d_out;
    int B = in_sizes[0] / (PS * PS);
    int nblocks = (B + WPB - 1) / WPB;
    orient_kernel<<<nblocks, THREADS>>>(x, gk, out, B);
}